// round 2
// baseline (speedup 1.0000x reference)
#include <cuda_runtime.h>

#define NN 4096
#define FIN 128
#define FO 64
#define HH 4
#define CC 512   // 256 proj cols (h*64+o) + 256 skip cols

// ---------------- scratch (static device globals; no allocation) ----------------
__device__ float  g_emask[(size_t)NN * NN];   // exp(mask), 64 MB
__device__ float  g_hidden[(size_t)NN * CC];  // [n][c]: c<256 proj, c>=256 skip (8 MB)
__device__ float  g_Wc[FIN * CC];             // combined weights [f][c]
__device__ float4 g_A[HH * NN];               // per (h,i): a, e^a, e^{0.2a}, -
__device__ float4 g_B[HH * NN];               // per (h,j): b, e^b, e^{0.2b}, invZ

// ---------------- helpers ----------------
__device__ __forceinline__ float2 unpack2(unsigned long long v) {
    float2 r; asm("mov.b64 {%0,%1}, %2;" : "=f"(r.x), "=f"(r.y) : "l"(v)); return r;
}
__device__ __forceinline__ void fma2(unsigned long long& acc, unsigned long long a, unsigned long long b) {
    asm("fma.rn.f32x2 %0, %1, %2, %0;" : "+l"(acc) : "l"(a), "l"(b));
}
__device__ __forceinline__ float maskf(float d, float b, float cut) {
    float wdm = d + b;
    return wdm > 0.f ? wdm : (b > cut ? (b + wdm) : -1e9f);
}

// ---------------- K0: build combined weight matrix Wc[f][c] ----------------
__global__ void k0_weights(const float* __restrict__ projp, const float* __restrict__ skw) {
    int idx = blockIdx.x * 256 + threadIdx.x;   // 128*512 = 65536
    int f = idx >> 9, c = idx & 511;
    float v;
    if (c < 256) v = projp[(c >> 6) * (FIN * FO) + f * FO + (c & 63)];
    else         v = skw[(c - 256) * FIN + f];
    g_Wc[idx] = v;
}

// ---------------- K1: hidden = nodes[4096,128] @ Wc[128,512] ----------------
__global__ void __launch_bounds__(256) k1_gemm(const float* __restrict__ nodes) {
    __shared__ float sN[32 * 128];
    __shared__ float sW[128 * 64];
    const int t = threadIdx.x;
    const int i0 = blockIdx.x * 32;
    const int c0 = blockIdx.y * 64;
#pragma unroll
    for (int k = 0; k < 4; k++) {
        int q = t + k * 256;                    // 1024 float4 of node tile (contiguous)
        ((float4*)sN)[q] = ((const float4*)(nodes + (size_t)i0 * FIN))[q];
    }
#pragma unroll
    for (int k = 0; k < 8; k++) {
        int idx = t + k * 256;                  // 2048 float4 of W tile
        int f = idx >> 4, q = idx & 15;
        *(float4*)(sW + f * 64 + q * 4) = *(const float4*)(g_Wc + f * CC + c0 + q * 4);
    }
    __syncthreads();
    const int c = t & 63, rg = t >> 6;          // 64 cols x 4 row-groups (8 rows each)
    float acc[8] = {0.f,0.f,0.f,0.f,0.f,0.f,0.f,0.f};
#pragma unroll 4
    for (int f = 0; f < 128; f++) {
        float wv = sW[f * 64 + c];
#pragma unroll
        for (int r = 0; r < 8; r++)
            acc[r] += sN[(rg * 8 + r) * 128 + f] * wv;
    }
#pragma unroll
    for (int r = 0; r < 8; r++)
        g_hidden[(size_t)(i0 + rg * 8 + r) * CC + c0 + c] = acc[r];
}

// ---------------- K2: per-(h,n) scores a,b and their exponentials ----------------
__global__ void __launch_bounds__(256) k2_scores(const float* __restrict__ ssrc,
                                                 const float* __restrict__ stgt) {
    int w = blockIdx.x * 8 + (threadIdx.x >> 5);    // one warp per (h,n)
    int lane = threadIdx.x & 31;
    int h = w >> 12, n = w & (NN - 1);
    const float* pr = g_hidden + (size_t)n * CC + h * FO;
    float p0 = pr[lane], p1 = pr[lane + 32];
    float sa = p0 * ssrc[h * FO + lane] + p1 * ssrc[h * FO + lane + 32];
    float sb = p0 * stgt[h * FO + lane] + p1 * stgt[h * FO + lane + 32];
#pragma unroll
    for (int o = 16; o > 0; o >>= 1) {
        sa += __shfl_xor_sync(0xffffffffu, sa, o);
        sb += __shfl_xor_sync(0xffffffffu, sb, o);
    }
    if (lane == 0) {
        g_A[h * NN + n] = make_float4(sa, __expf(sa), __expf(0.2f * sa), 0.f);
        g_B[h * NN + n] = make_float4(sb, __expf(sb), __expf(0.2f * sb), 0.f);
    }
}

// ---------------- K3: mask -> emask + LayerNorm(mask) in one row pass ----------------
__global__ void __launch_bounds__(256) k3_mask(const float* __restrict__ deg,
                                               const float* __restrict__ bond,
                                               const float* __restrict__ cutp,
                                               float* __restrict__ out_ln) {
    __shared__ float srow[NN];
    __shared__ float red1[256], red2[256];
    const int i = blockIdx.x;
    const int t = threadIdx.x;
    const float cut = cutp[0];
    const float4* d4 = (const float4*)(deg  + (size_t)i * NN);
    const float4* b4 = (const float4*)(bond + (size_t)i * NN);
    float4* e4 = (float4*)(g_emask + (size_t)i * NN);
    float s = 0.f, sq = 0.f;
#pragma unroll
    for (int k = 0; k < 4; k++) {
        int q = t + k * 256;
        float4 dv = d4[q], bv = b4[q];
        float4 mv;
        mv.x = maskf(dv.x, bv.x, cut);
        mv.y = maskf(dv.y, bv.y, cut);
        mv.z = maskf(dv.z, bv.z, cut);
        mv.w = maskf(dv.w, bv.w, cut);
        ((float4*)srow)[q] = mv;
        e4[q] = make_float4(__expf(mv.x), __expf(mv.y), __expf(mv.z), __expf(mv.w));
        s  += (mv.x + mv.y) + (mv.z + mv.w);
        sq += mv.x * mv.x + mv.y * mv.y + mv.z * mv.z + mv.w * mv.w;
    }
    red1[t] = s; red2[t] = sq;
    __syncthreads();
    for (int o = 128; o > 0; o >>= 1) {
        if (t < o) { red1[t] += red1[t + o]; red2[t] += red2[t + o]; }
        __syncthreads();
    }
    float mu  = red1[0] * (1.f / NN);
    float var = red2[0] * (1.f / NN) - mu * mu;
    float rs  = rsqrtf(var + 1e-5f);
    float4* o4 = (float4*)(out_ln + (size_t)i * NN);
#pragma unroll
    for (int k = 0; k < 4; k++) {
        int q = t + k * 256;
        float4 mv = ((float4*)srow)[q];
        o4[q] = make_float4((mv.x - mu) * rs, (mv.y - mu) * rs,
                            (mv.z - mu) * rs, (mv.w - mu) * rs);
    }
}

// ---------------- K5: column sums -> invZ[h][j] (no atomics) ----------------
__global__ void __launch_bounds__(256) k5_colsum() {
    __shared__ float4 sA[4 * 256];
    __shared__ float sS1[4 * 8 * 32];
    __shared__ float sS2[4 * 8 * 32];
    const int t = threadIdx.x;
    const int j0 = blockIdx.x * 32;
    const int col = t & 31, seg = t >> 5;
    const int j = j0 + col;
    float thr[4];
#pragma unroll
    for (int h = 0; h < 4; h++) thr[h] = -g_B[h * NN + j].x;
    float S1[4] = {0,0,0,0}, S2[4] = {0,0,0,0};
    for (int c0 = 0; c0 < NN; c0 += 256) {
        __syncthreads();
#pragma unroll
        for (int k = 0; k < 4; k++) {
            int idx = t + k * 256;                       // 1024 = 4 heads x 256 rows
            sA[idx] = g_A[(idx >> 8) * NN + c0 + (idx & 255)];
        }
        __syncthreads();
        const float* emp = g_emask + (size_t)(c0 + seg * 32) * NN + j;
#pragma unroll 4
        for (int s = 0; s < 32; s++) {
            float em = emp[(size_t)s * NN];
#pragma unroll
            for (int h = 0; h < 4; h++) {
                float4 av = sA[h * 256 + seg * 32 + s];
                if (av.x > thr[h]) S1[h] += av.y * em; else S2[h] += av.z * em;
            }
        }
    }
#pragma unroll
    for (int h = 0; h < 4; h++) {
        sS1[(h * 8 + seg) * 32 + col] = S1[h];
        sS2[(h * 8 + seg) * 32 + col] = S2[h];
    }
    __syncthreads();
    if (t < 128) {
        int h = t >> 5, c = t & 31;
        float z1 = 0.f, z2 = 0.f;
#pragma unroll
        for (int s = 0; s < 8; s++) { z1 += sS1[(h * 8 + s) * 32 + c]; z2 += sS2[(h * 8 + s) * 32 + c]; }
        float4 Bv = g_B[h * NN + j0 + c];
        float Z = Bv.y * z1 + Bv.z * z2;
        ((float*)&g_B[h * NN + j0 + c])[3] = 1.0f / Z;
    }
}

// ---------------- K4: out = attn @ proj + skip, ELU (f32x2 FMA) ----------------
// block: head h, 32 rows; 256 threads. Per 128-wide j tile:
//   phase A: w[i][j] = sel(a_i>-b_j)? eA*eB*invZ : eA2*eB2*invZ, * emask  (stored as (w,w) float2)
//   phase B: acc(f-pair) += proj[j][f-pair] * (w,w) via fma.rn.f32x2
__global__ void __launch_bounds__(256) k4_agg(float* __restrict__ out) {
    extern __shared__ float sm[];
    float*  sProj = sm;                          // 128*64 = 8192 floats
    float2* sW2   = (float2*)(sm + 8192);        // 128 rows * stride 34 float2 = 8704 floats
    float4* sAr   = (float4*)(sm + 8192 + 8704); // 32 float4
    const int i0 = blockIdx.x * 32;
    const int h  = blockIdx.y;
    const int t  = threadIdx.x;
    const int jl = t & 127, ihalf = t >> 7;      // phase A mapping
    const int fp = t & 31,  g = t >> 5;          // phase B mapping: f-pair, row group
    if (t < 32) sAr[t] = g_A[h * NN + i0 + t];
    unsigned long long acc0 = 0ull, acc1 = 0ull, acc2 = 0ull, acc3 = 0ull;
    for (int j0 = 0; j0 < NN; j0 += 128) {
        __syncthreads();
        // stage proj tile [128][64]
#pragma unroll
        for (int k = 0; k < 8; k++) {
            int idx = t + k * 256;
            int jr = idx >> 4, q = idx & 15;
            *(float4*)(sProj + jr * 64 + q * 4) =
                *(const float4*)(g_hidden + (size_t)(j0 + jr) * CC + h * FO + q * 4);
        }
        float4 Bv = g_B[h * NN + j0 + jl];
        float thr = -Bv.x;
        float e1 = Bv.y * Bv.w;   // e^b * invZ
        float e2 = Bv.z * Bv.w;   // e^{0.2b} * invZ
        const float* emrow = g_emask + (size_t)i0 * NN + j0 + jl;
#pragma unroll
        for (int s = 0; s < 16; s++) {
            int il = ihalf * 16 + s;
            float em = emrow[(size_t)il * NN];
            float4 av = sAr[il];
            float v = (av.x > thr) ? (av.y * e1) : (av.z * e2);
            float w = v * em;
            sW2[jl * 34 + ((il & 7) * 4 + (il >> 3))] = make_float2(w, w);
        }
        __syncthreads();
#pragma unroll 8
        for (int jj = 0; jj < 128; jj++) {
            unsigned long long p = *(const unsigned long long*)(sProj + jj * 64 + fp * 2);
            ulonglong2 wa = *(const ulonglong2*)(sW2 + jj * 34 + g * 4);
            ulonglong2 wb = *(const ulonglong2*)(sW2 + jj * 34 + g * 4 + 2);
            fma2(acc0, p, wa.x);   // row g
            fma2(acc1, p, wa.y);   // row g+8
            fma2(acc2, p, wb.x);   // row g+16
            fma2(acc3, p, wb.y);   // row g+24
        }
    }
    unsigned long long accs[4] = {acc0, acc1, acc2, acc3};
#pragma unroll
    for (int k = 0; k < 4; k++) {
        int i = i0 + g + 8 * k;
        float2 a = unpack2(accs[k]);
        const float2 sk = *(const float2*)(g_hidden + (size_t)i * CC + 256 + h * FO + fp * 2);
        float x0 = a.x + sk.x, x1 = a.y + sk.y;
        x0 = x0 > 0.f ? x0 : (__expf(x0) - 1.f);
        x1 = x1 > 0.f ? x1 : (__expf(x1) - 1.f);
        *(float2*)(out + (size_t)i * 256 + h * FO + fp * 2) = make_float2(x0, x1);
    }
}

// ---------------- launcher ----------------
extern "C" void kernel_launch(void* const* d_in, const int* in_sizes, int n_in,
                              void* d_out, int out_size) {
    const float* nodes = (const float*)d_in[0];
    const float* degm  = (const float*)d_in[1];
    // d_in[2] = edges_features_distance (unused by reference)
    const float* bond  = (const float*)d_in[3];
    const float* projp = (const float*)d_in[4];
    const float* ssrc  = (const float*)d_in[5];
    const float* stgt  = (const float*)d_in[6];
    const float* skw   = (const float*)d_in[7];
    const float* cutp  = (const float*)d_in[8];  // value 0: any-dtype zero reads as 0.0f
    float* out = (float*)d_out;

    k0_weights<<<256, 256>>>(projp, skw);
    k1_gemm<<<dim3(128, 8), 256>>>(nodes);
    k2_scores<<<2048, 256>>>(ssrc, stgt);
    k3_mask<<<4096, 256>>>(degm, bond, cutp, out + (size_t)NN * 256);
    k5_colsum<<<128, 256>>>();

    const int smem4 = (8192 + 8704 + 128) * 4;   // 68096 bytes
    cudaFuncSetAttribute(k4_agg, cudaFuncAttributeMaxDynamicSharedMemorySize, smem4);
    k4_agg<<<dim3(128, 4), 256, smem4>>>(out);
}